// round 1
// baseline (speedup 1.0000x reference)
#include <cuda_runtime.h>
#include <cstdint>

// Problem constants (fixed shapes)
#define BATCH   64
#define SEQ     8192
#define RDIM    80
#define NTAPS   5
#define MAXD    168
#define NTHREADS 320        // (i in 0..79) x (jh in 0..3)
#define JSLICE  20          // j elements per thread per tap
#define NPAIR   10          // f32x2 pairs per tap per thread

typedef unsigned long long u64;

__device__ __forceinline__ u64 ffma2(u64 a, u64 b, u64 c) {
    u64 d;
    asm("fma.rn.f32x2 %0, %1, %2, %3;" : "=l"(d) : "l"(a), "l"(b), "l"(c));
    return d;
}

__device__ __forceinline__ float2 unpack2(u64 v) {
    unsigned lo, hi;
    asm("mov.b64 {%0, %1}, %2;" : "=r"(lo), "=r"(hi) : "l"(v));
    float2 r;
    r.x = __uint_as_float(lo);
    r.y = __uint_as_float(hi);
    return r;
}

__global__ __launch_bounds__(NTHREADS, 1)
void reservoir_kernel(const float* __restrict__ x,
                      const float* __restrict__ Win,
                      const float* __restrict__ Wfb,
                      const float* __restrict__ bias,
                      float* __restrict__ out)
{
    extern __shared__ float sm[];
    float* Hring   = sm;                       // [MAXD][RDIM]  = 13440 f
    float* xs      = Hring + MAXD * RDIM;      // [SEQ]         = 8192 f
    float* partial = xs + SEQ;                 // [4][RDIM]     = 320 f

    const int b   = blockIdx.x;
    const int tid = threadIdx.x;
    const int i   = tid % RDIM;   // output index
    const int jh  = tid / RDIM;   // j-quarter 0..3

    // Zero the state ring (states before t=0 are zero)
    for (int idx = tid; idx < MAXD * RDIM; idx += NTHREADS) Hring[idx] = 0.0f;

    // Stage this batch's input sequence into smem (INPUT_DIM == 1)
    const float* xb = x + (size_t)b * SEQ;
    for (int idx = tid; idx < SEQ; idx += NTHREADS) xs[idx] = xb[idx];

    // Load this thread's W_fb slice into registers as f32x2 pairs.
    // feedback[i] = sum_k sum_j delayed[k][j] * Wfb[k][i][j]
    u64 Wp[NTAPS][NPAIR];
#pragma unroll
    for (int k = 0; k < NTAPS; k++) {
        const float* wrow = Wfb + ((size_t)k * RDIM + i) * RDIM + jh * JSLICE;
#pragma unroll
        for (int p = 0; p < NPAIR; p++) {
            unsigned lo = __float_as_uint(wrow[2 * p]);
            unsigned hi = __float_as_uint(wrow[2 * p + 1]);
            Wp[k][p] = ((u64)hi << 32) | (u64)lo;
        }
    }

    float win_i = 0.0f, bias_i = 0.0f, h_i = 0.0f;
    if (tid < RDIM) { win_i = Win[tid]; bias_i = bias[tid]; }

    float* outb = out + (size_t)b * SEQ * RDIM;

    __syncthreads();

    int s = 0;  // t mod MAXD (write slot for h[t])
    for (int t = 0; t < SEQ; ++t) {
        // Ring slots for taps {1,4,24,96,168}. Slot (t - tau) mod MAXD holds
        // h[t-tau]; if t < tau that slot hasn't been written yet -> still 0.
        int s0 = s - 1;   if (s0 < 0) s0 += MAXD;
        int s1 = s - 4;   if (s1 < 0) s1 += MAXD;
        int s2 = s - 24;  if (s2 < 0) s2 += MAXD;
        int s3 = s - 96;  if (s3 < 0) s3 += MAXD;
        int s4 = s;       // tau == MAXD
        int slot[NTAPS] = { s0, s1, s2, s3, s4 };

        u64 acc0 = 0ull, acc1 = 0ull;  // {0.f,0.f} bitwise
#pragma unroll
        for (int k = 0; k < NTAPS; k++) {
            const float* hrow = Hring + slot[k] * RDIM + jh * JSLICE;
            const ulonglong2* hv = reinterpret_cast<const ulonglong2*>(hrow);
#pragma unroll
            for (int p = 0; p < NPAIR / 2; p++) {
                ulonglong2 hh = hv[p];                    // LDS.128: 4 delayed vals
                acc0 = ffma2(hh.x, Wp[k][2 * p],     acc0);
                acc1 = ffma2(hh.y, Wp[k][2 * p + 1], acc1);
            }
        }

        float2 a0 = unpack2(acc0);
        float2 a1 = unpack2(acc1);
        partial[jh * RDIM + i] = (a0.x + a0.y) + (a1.x + a1.y);
        __syncthreads();

        if (tid < RDIM) {
            float f = partial[tid] + partial[RDIM + tid] +
                      partial[2 * RDIM + tid] + partial[3 * RDIM + tid];
            float val = xs[t] * win_i + f + bias_i;
            h_i = 0.7f * h_i + 0.3f * tanhf(val);
            Hring[s * RDIM + tid] = h_i;
            outb[(size_t)t * RDIM + tid] = h_i;
        }
        __syncthreads();

        if (++s == MAXD) s = 0;
    }
}

extern "C" void kernel_launch(void* const* d_in, const int* in_sizes, int n_in,
                              void* d_out, int out_size)
{
    const float* x    = (const float*)d_in[0];  // [64, 8192, 1]
    const float* Win  = (const float*)d_in[1];  // [80, 1]
    const float* Wfb  = (const float*)d_in[2];  // [5, 80, 80]
    const float* bias = (const float*)d_in[3];  // [80]
    float* out = (float*)d_out;                 // [64, 8192, 80]

    const int smem_bytes = (MAXD * RDIM + SEQ + 4 * RDIM) * sizeof(float);
    cudaFuncSetAttribute(reservoir_kernel,
                         cudaFuncAttributeMaxDynamicSharedMemorySize, smem_bytes);

    reservoir_kernel<<<BATCH, NTHREADS, smem_bytes>>>(x, Win, Wfb, bias, out);
}